// round 2
// baseline (speedup 1.0000x reference)
#include <cuda_runtime.h>
#include <cuda_bf16.h>

// Problem constants (fixed shapes)
#define B_DIM 2
#define N_DIM 1024
#define S_DIM 256          // SINGLE_DIM
#define P_DIM 64           // PAIR_DIM
#define MAX_REL 32
#define EMBED_ROWS (2 * MAX_REL + 1)   // 65
#define LN_EPS 1e-5f

// Scratch for projections: (B*N, 64) each -> __device__ globals (no cudaMalloc allowed).
__device__ float g_proj_i[B_DIM * N_DIM * P_DIM];
__device__ float g_proj_j[B_DIM * N_DIM * P_DIM];

// ---------------------------------------------------------------------------
// Kernel A: fused projection GEMM (tiny: 2048x512 @ 512x64-equivalent).
// Block = 16 rows staged in shared, 128 threads: t<64 -> W_i col, t>=64 -> W_j col.
// ---------------------------------------------------------------------------
#define ROWS_PER_BLK 16

__global__ __launch_bounds__(128, 8)
void proj_kernel(const float* __restrict__ single_repr,
                 const float* __restrict__ W,
                 float* __restrict__ proj_i,
                 float* __restrict__ proj_j)
{
    __shared__ float sh[ROWS_PER_BLK][S_DIM];

    const int t    = threadIdx.x;          // 0..127
    const int row0 = blockIdx.x * ROWS_PER_BLK;

    const float4* s4  = reinterpret_cast<const float4*>(single_repr + (size_t)row0 * S_DIM);
    float4*       sh4 = reinterpret_cast<float4*>(&sh[0][0]);
#pragma unroll
    for (int k = 0; k < 8; ++k)
        sh4[t + 128 * k] = s4[t + 128 * k];
    __syncthreads();

    const int col  = t & 63;
    const int half = t >> 6;   // 0 -> W_i, 1 -> W_j
    const float* Wp = W + (size_t)half * S_DIM * P_DIM + col;

    float acc[ROWS_PER_BLK];
#pragma unroll
    for (int r = 0; r < ROWS_PER_BLK; ++r) acc[r] = 0.f;

#pragma unroll 4
    for (int d = 0; d < S_DIM; ++d) {
        const float w = Wp[(size_t)d * P_DIM];
#pragma unroll
        for (int r = 0; r < ROWS_PER_BLK; ++r)
            acc[r] = fmaf(sh[r][d], w, acc[r]);
    }

    float* out = half ? proj_j : proj_i;
#pragma unroll
    for (int r = 0; r < ROWS_PER_BLK; ++r)
        out[(size_t)(row0 + r) * P_DIM + col] = acc[r];
}

// ---------------------------------------------------------------------------
// Kernel B: pairwise LayerNorm + ReLU + rel-pos embedding.
// One block per (b, i). 8 warps. Each warp handles TWO j-rows per iteration:
//   group  = lane >> 4  (0/1 -> row j+0 / j+1)
//   sub    = lane & 15  -> lane owns float4 elements [4*sub .. 4*sub+3]
// LN reduction: 4-round shfl-xor butterfly within the 16-lane group
// (offsets 8,4,2,1 never cross bit 4). 4 SHFL per row vs 10 for warp-per-row.
// Loads/stores are float4 (128-bit), warp covers 512 B contiguous.
// ---------------------------------------------------------------------------
__global__ __launch_bounds__(256, 8)
void pair_kernel(const float* __restrict__ proj_i,
                 const float* __restrict__ proj_j,
                 const float* __restrict__ bias,
                 const float* __restrict__ gamma,
                 const float* __restrict__ beta,
                 const float* __restrict__ embed,
                 float* __restrict__ out)
{
    __shared__ float sh_embed[EMBED_ROWS * P_DIM];   // 16.25 KB

    const int bi = blockIdx.x;            // 0 .. B*N-1
    const int bb = bi >> 10;              // batch index
    const int i  = bi & (N_DIM - 1);      // position i

    // Stage embed table in shared.
    {
        const float4* e4  = reinterpret_cast<const float4*>(embed);
        float4*       se4 = reinterpret_cast<float4*>(sh_embed);
        for (int k = threadIdx.x; k < (EMBED_ROWS * P_DIM) / 4; k += 256)
            se4[k] = e4[k];
    }

    const int warp  = threadIdx.x >> 5;
    const int lane  = threadIdx.x & 31;
    const int group = lane >> 4;          // which of the two j-rows
    const int sub   = lane & 15;          // position within the 64-wide row

    // Per-lane constants for row i (same for both groups).
    float4 pi = reinterpret_cast<const float4*>(proj_i + (size_t)bi * P_DIM)[sub];
    {
        const float4 b4 = reinterpret_cast<const float4*>(bias)[sub];
        pi.x += b4.x; pi.y += b4.y; pi.z += b4.z; pi.w += b4.w;
    }
    const float4 g4  = reinterpret_cast<const float4*>(gamma)[sub];
    const float4 be4 = reinterpret_cast<const float4*>(beta)[sub];

    __syncthreads();

    // proj_j row (j = 2*warp + group + 16*iter), float4 at position sub.
    const float4* pj_base = reinterpret_cast<const float4*>(
        proj_j + (size_t)bb * N_DIM * P_DIM) + group * (P_DIM / 4) + sub;
    float4* out_base = reinterpret_cast<float4*>(
        out + (size_t)bi * N_DIM * P_DIM) + group * (P_DIM / 4) + sub;

    int j0 = 2 * warp;                    // first j-pair handled by this warp
#pragma unroll 4
    for (int it = 0; it < N_DIM / 16; ++it) {
        const int j = j0 + it * 16;       // this lane's row is j + group
        const float4 pj = pj_base[(size_t)j * (P_DIM / 4)];

        float4 v;
        v.x = pi.x + pj.x;
        v.y = pi.y + pj.y;
        v.z = pi.z + pj.z;
        v.w = pi.w + pj.w;

        float s  = (v.x + v.y) + (v.z + v.w);
        float sq = fmaf(v.x, v.x, fmaf(v.y, v.y, fmaf(v.z, v.z, v.w * v.w)));
#pragma unroll
        for (int off = 8; off > 0; off >>= 1) {
            s  += __shfl_xor_sync(0xFFFFFFFFu, s,  off);
            sq += __shfl_xor_sync(0xFFFFFFFFu, sq, off);
        }

        const float mu  = s * (1.f / P_DIM);
        const float var = fmaf(sq, 1.f / P_DIM, -mu * mu);
        const float inv = rsqrtf(var + LN_EPS);

        int rel = (j + group) - i;
        rel = (rel < -MAX_REL) ? -MAX_REL : (rel > MAX_REL ? MAX_REL : rel);
        const float4 e = reinterpret_cast<const float4*>(
            sh_embed + (rel + MAX_REL) * P_DIM)[sub];

        float4 y;
        y.x = fmaxf((v.x - mu) * inv * g4.x + be4.x, 0.f) + e.x;
        y.y = fmaxf((v.y - mu) * inv * g4.y + be4.y, 0.f) + e.y;
        y.z = fmaxf((v.z - mu) * inv * g4.z + be4.z, 0.f) + e.z;
        y.w = fmaxf((v.w - mu) * inv * g4.w + be4.w, 0.f) + e.w;

        out_base[(size_t)j * (P_DIM / 4)] = y;
    }
}

// ---------------------------------------------------------------------------
extern "C" void kernel_launch(void* const* d_in, const int* in_sizes, int n_in,
                              void* d_out, int out_size)
{
    const float* single_repr = (const float*)d_in[0];  // (2,1024,256)
    const float* W           = (const float*)d_in[1];  // (512,64)
    const float* bias        = (const float*)d_in[2];  // (64,)
    const float* gamma       = (const float*)d_in[3];  // (64,)
    const float* beta        = (const float*)d_in[4];  // (64,)
    const float* embed       = (const float*)d_in[5];  // (65,64)
    float* out = (float*)d_out;                        // (2,1024,1024,64)

    float* proj_i_ptr; float* proj_j_ptr;
    cudaGetSymbolAddress((void**)&proj_i_ptr, g_proj_i);
    cudaGetSymbolAddress((void**)&proj_j_ptr, g_proj_j);

    const int total_rows = B_DIM * N_DIM;  // 2048

    proj_kernel<<<total_rows / ROWS_PER_BLK, 128>>>(single_repr, W, proj_i_ptr, proj_j_ptr);
    pair_kernel<<<total_rows, 256>>>(proj_i_ptr, proj_j_ptr, bias, gamma, beta, embed, out);
}